// round 1
// baseline (speedup 1.0000x reference)
#include <cuda_runtime.h>

#define BB 2
#define HH 48
#define WW 48
#define CC 96
#define LL 2304      // HH*WW
#define DI 192       // D_INNER
#define NS 32        // D_STATE
#define RR 6         // DT_RANK
#define KK 4

// ---------------- scratch (device globals; no runtime alloc) ----------------
__device__ float g_z[BB*LL*DI];        // gate input  [b,l,d]
__device__ float g_xpre[BB*DI*LL];     // pre-conv x  [b,d,h,w]
__device__ float g_conv[BB*DI*LL];     // conv+silu   [b,d,h,w]
__device__ float g_dtr[BB*KK*LL*RR];   // dt_rank     [b,k,l,r]
__device__ float g_Bs[BB*KK*LL*NS];    // B           [b,k,l,n]
__device__ float g_Cs[BB*KK*LL*NS];    // C           [b,k,l,n]
__device__ float g_delta[BB*KK*DI*LL]; // softplus dt [b,k,d,l]
__device__ float g_y[BB*LL*DI];        // merged scan output [b,l,d]

// ---------------- zero y accumulator ----------------
__global__ void k_zero() {
    int i = blockIdx.x*1024 + threadIdx.x;   // 864*1024 == BB*LL*DI
    g_y[i] = 0.f;
}

// ---------------- in_proj: xz[m,e] = sum_c x[m,c]*W[e,c] ----------------
// grid 288, block 384: each block does 16 rows (m) x all 384 e.
__global__ void __launch_bounds__(384) k_inproj(const float* __restrict__ x,
                                                const float* __restrict__ W) {
    __shared__ float xt[16][CC];
    int m0 = blockIdx.x * 16;
    int tid = threadIdx.x;
    for (int i = tid; i < 16*CC; i += 384)
        xt[i/CC][i%CC] = x[(m0 + i/CC)*CC + i%CC];
    __syncthreads();

    int e = tid;
    float acc[16];
#pragma unroll
    for (int i = 0; i < 16; i++) acc[i] = 0.f;
    const float* wrow = W + e*CC;
#pragma unroll 4
    for (int c = 0; c < CC; c++) {
        float w = wrow[c];
#pragma unroll
        for (int i = 0; i < 16; i++) acc[i] = fmaf(w, xt[i][c], acc[i]);
    }
    if (e < DI) {
#pragma unroll
        for (int i = 0; i < 16; i++) {
            int m = m0 + i; int b = m / LL; int l = m % LL;
            g_xpre[(b*DI + e)*LL + l] = acc[i];
        }
    } else {
        int e2 = e - DI;
#pragma unroll
        for (int i = 0; i < 16; i++) g_z[(m0+i)*DI + e2] = acc[i];
    }
}

// ---------------- depthwise 3x3 conv + bias + silu ----------------
__global__ void k_conv(const float* __restrict__ cw, const float* __restrict__ cb) {
    int idx = blockIdx.x*256 + threadIdx.x;
    if (idx >= BB*DI*LL) return;
    int w = idx % WW;
    int h = (idx/WW) % HH;
    int d = (idx/LL) % DI;
    int b = idx/(LL*DI);
    const float* base = g_xpre + (b*DI + d)*LL;
    const float* wt = cw + d*9;
    float s = cb[d];
#pragma unroll
    for (int kh = -1; kh <= 1; kh++) {
        int h2 = h + kh;
        if (h2 < 0 || h2 >= HH) continue;
#pragma unroll
        for (int kw = -1; kw <= 1; kw++) {
            int w2 = w + kw;
            if (w2 < 0 || w2 >= WW) continue;
            s = fmaf(base[h2*WW + w2], wt[(kh+1)*3 + (kw+1)], s);
        }
    }
    g_conv[idx] = s / (1.f + __expf(-s));   // silu
}

// ---------------- x_proj: x_dbl[b,k,c,l] = sum_d xs[b,k,d,l]*xpw[k,c,d] ------
// grid (72 l-tiles, 2 axes, 2 b), block 256.
// One forward tile serves both k=axis (forward) and k=axis+2 (flipped: output
// index L-1-l with the k+2 weights).
__global__ void __launch_bounds__(256) k_xdbl(const float* __restrict__ xpw) {
    __shared__ float tile[DI][33];
    int lt0  = blockIdx.x * 32;
    int axis = blockIdx.y;
    int b    = blockIdx.z;
    int tid  = threadIdx.x;

    for (int i = tid; i < DI*32; i += 256) {
        int d = i >> 5, lc = i & 31;
        int l = lt0 + lc;
        int pos;
        if (axis == 0) pos = l;
        else { int q = (l*21846) >> 20; pos = (l - q*48)*48 + q; }  // (l%48)*48 + l/48
        tile[d][lc] = g_conv[(b*DI + d)*LL + pos];
    }
    __syncthreads();

    int lc = tid & 31;
    int cg = tid >> 5;          // 0..7
    int l  = lt0 + lc;
    for (int s = 0; s < 18; s++) {
        int c2 = cg*18 + s;
        if (c2 >= 140) break;           // warp-uniform
        int flip = (c2 >= 70) ? 1 : 0;
        int c = c2 - flip*70;
        int k = axis + flip*2;
        const float* wrow = xpw + (k*70 + c)*DI;
        float acc = 0.f;
#pragma unroll 8
        for (int d = 0; d < DI; d++) acc = fmaf(tile[d][lc], wrow[d], acc);
        int lo  = flip ? (LL-1-l) : l;
        int bkl = (b*KK + k)*LL + lo;
        if (c < RR)            g_dtr[bkl*RR + c]            = acc;
        else if (c < RR+NS)    g_Bs [bkl*NS + (c-RR)]       = acc;
        else                   g_Cs [bkl*NS + (c-RR-NS)]    = acc;
    }
}

// ---------------- dt expansion + softplus ----------------
// grid (72, 6, 8=b*K), block (32 l, 32 d)
__global__ void __launch_bounds__(1024) k_delta(const float* __restrict__ dtw,
                                                const float* __restrict__ dtb) {
    int l  = blockIdx.x*32 + threadIdx.x;
    int d  = blockIdx.y*32 + threadIdx.y;
    int bk = blockIdx.z;
    int k  = bk % KK;
    const float* r = g_dtr + (bk*LL + l)*RR;
    const float* w = dtw + (k*DI + d)*RR;
    float acc = dtb[k*DI + d];
#pragma unroll
    for (int j = 0; j < RR; j++) acc = fmaf(r[j], w[j], acc);
    float sp = (acc > 20.f) ? acc : log1pf(expf(acc));
    g_delta[(bk*DI + d)*LL + l] = sp;
}

// ---------------- selective scan: 1 warp per (b,k,d), lane = state ----------
__global__ void __launch_bounds__(256) k_scan(const float* __restrict__ A_logs,
                                              const float* __restrict__ Ds) {
    int wg   = (blockIdx.x*256 + threadIdx.x) >> 5;
    int lane = threadIdx.x & 31;
    int d = wg % DI;
    int k = (wg/DI) % KK;
    int b = wg / (DI*KK);
    int kd = k*DI + d;

    float A  = -__expf(A_logs[kd*NS + lane]);
    float Dv = Ds[kd];
    const float* pd = g_delta + ((b*KK + k)*DI + d)*LL;
    const float* pB = g_Bs + (b*KK + k)*LL*NS + lane;
    const float* pC = g_Cs + (b*KK + k)*LL*NS + lane;
    const float* pu = g_conv + (b*DI + d)*LL;
    float* py = g_y + b*LL*DI + d;
    int axis = k & 1, rev = k >> 1;

    float h = 0.f;
    for (int l0 = 0; l0 < LL; l0 += 4) {
#pragma unroll
        for (int j = 0; j < 4; j++) {
            int l = l0 + j;
            float delta = pd[l];
            int m = rev ? (LL-1-l) : l;
            int pos;
            if (axis == 0) pos = m;
            else { int q = (m*21846) >> 20; pos = (m - q*48)*48 + q; }
            float u  = pu[pos];
            float Bv = pB[l*NS];
            float Cv = pC[l*NS];
            float dA = __expf(delta * A);
            h = fmaf(h, dA, (delta*u) * Bv);
            float p = h * Cv;
            p += __shfl_xor_sync(0xffffffffu, p, 16);
            p += __shfl_xor_sync(0xffffffffu, p, 8);
            p += __shfl_xor_sync(0xffffffffu, p, 4);
            p += __shfl_xor_sync(0xffffffffu, p, 2);
            p += __shfl_xor_sync(0xffffffffu, p, 1);
            if (lane == 0) atomicAdd(py + pos*DI, fmaf(Dv, u, p));
        }
    }
}

// ---------------- LayerNorm + gate + out_proj + residual ----------------
// grid B*L, block 192
__global__ void __launch_bounds__(192) k_final(const float* __restrict__ x,
                                               const float* __restrict__ lnw,
                                               const float* __restrict__ lnb,
                                               const float* __restrict__ Wo,
                                               float* __restrict__ out) {
    __shared__ float yg[DI];
    __shared__ float red[16];
    __shared__ float part[DI];
    int bl = blockIdx.x;
    int t  = threadIdx.x;

    float v = g_y[bl*DI + t];
    float s = v, ss = v*v;
#pragma unroll
    for (int o = 16; o > 0; o >>= 1) {
        s  += __shfl_xor_sync(0xffffffffu, s,  o);
        ss += __shfl_xor_sync(0xffffffffu, ss, o);
    }
    if ((t & 31) == 0) { red[t>>5] = s; red[8 + (t>>5)] = ss; }
    __syncthreads();
    if (t == 0) {
        float S = 0.f, SS = 0.f;
        for (int i = 0; i < 6; i++) { S += red[i]; SS += red[8+i]; }
        red[14] = S; red[15] = SS;
    }
    __syncthreads();
    float mu  = red[14] * (1.f/DI);
    float var = red[15] * (1.f/DI) - mu*mu;
    float inv = rsqrtf(var + 1e-5f);
    float z   = g_z[bl*DI + t];
    float sil = z / (1.f + __expf(-z));
    yg[t] = ((v - mu)*inv*lnw[t] + lnb[t]) * sil;
    __syncthreads();

    int c  = (t < 96) ? t : t - 96;
    int h0 = (t < 96) ? 0 : 96;
    const float* wr = Wo + c*DI + h0;
    float acc = 0.f;
#pragma unroll 8
    for (int dd = 0; dd < 96; dd++) acc = fmaf(yg[h0 + dd], wr[dd], acc);
    part[t] = acc;
    __syncthreads();
    if (t < 96) out[bl*CC + t] = x[bl*CC + t] + part[t] + part[t + 96];
}

// ---------------- launch ----------------
extern "C" void kernel_launch(void* const* d_in, const int* in_sizes, int n_in,
                              void* d_out, int out_size) {
    const float* x    = (const float*)d_in[0];
    const float* ipw  = (const float*)d_in[1];
    const float* cw   = (const float*)d_in[2];
    const float* cb   = (const float*)d_in[3];
    const float* xpw  = (const float*)d_in[4];
    const float* dtw  = (const float*)d_in[5];
    const float* dtb  = (const float*)d_in[6];
    const float* alog = (const float*)d_in[7];
    const float* Dsp  = (const float*)d_in[8];
    const float* lnw  = (const float*)d_in[9];
    const float* lnb  = (const float*)d_in[10];
    const float* Wo   = (const float*)d_in[11];
    float* out = (float*)d_out;

    k_zero  <<<864, 1024>>>();
    k_inproj<<<288, 384>>>(x, ipw);
    k_conv  <<<(BB*DI*LL + 255)/256, 256>>>(cw, cb);
    k_xdbl  <<<dim3(72, 2, 2), 256>>>(xpw);
    k_delta <<<dim3(72, 6, 8), dim3(32, 32)>>>(dtw, dtb);
    k_scan  <<<192, 256>>>(alog, Dsp);
    k_final <<<BB*LL, 192>>>(x, lnw, lnb, Wo, out);
}

// round 4
// speedup vs baseline: 2.0803x; 2.0803x over previous
#include <cuda_runtime.h>

#define BB 2
#define HH 48
#define WW 48
#define CC 96
#define LL 2304      // HH*WW
#define DI 192       // D_INNER
#define NS 32        // D_STATE
#define RR 6         // DT_RANK
#define KK 4

// ---------------- scratch (device globals; no runtime alloc) ----------------
__device__ __align__(16) float g_z[BB*LL*DI];        // gate input  [b,l,d]
__device__ __align__(16) float g_xpre[BB*DI*LL];     // pre-conv x  [b,d,h,w]
__device__ __align__(16) float g_conv[BB*DI*LL];     // conv+silu   [b,d,h,w]
__device__ __align__(16) float g_convT[BB*DI*LL];    // transposed  [b,d,w,h]
__device__ __align__(16) float g_dtr[BB*KK*LL*RR];   // dt_rank     [b,k,l,r]
__device__ __align__(16) float g_Bs[BB*KK*LL*NS];    // B           [b,k,l,n]
__device__ __align__(16) float g_Cs[BB*KK*LL*NS];    // C           [b,k,l,n]
__device__ __align__(16) float g_delta[BB*KK*DI*LL]; // softplus dt [b,k,d,l]
__device__ __align__(16) float g_y[BB*LL*DI];        // merged scan output [b,l,d]

// ---------------- zero y accumulator ----------------
__global__ void k_zero() {
    int i = blockIdx.x*1024 + threadIdx.x;   // 864*1024 == BB*LL*DI
    g_y[i] = 0.f;
}

// ---------------- in_proj: xz[m,e] = sum_c x[m,c]*W[e,c] ----------------
__global__ void __launch_bounds__(384) k_inproj(const float* __restrict__ x,
                                                const float* __restrict__ W) {
    __shared__ float xt[16][CC];
    int m0 = blockIdx.x * 16;
    int tid = threadIdx.x;
    for (int i = tid; i < 16*CC; i += 384)
        xt[i/CC][i%CC] = x[(m0 + i/CC)*CC + i%CC];
    __syncthreads();

    int e = tid;
    float acc[16];
#pragma unroll
    for (int i = 0; i < 16; i++) acc[i] = 0.f;
    const float* wrow = W + e*CC;
#pragma unroll 4
    for (int c = 0; c < CC; c++) {
        float w = wrow[c];
#pragma unroll
        for (int i = 0; i < 16; i++) acc[i] = fmaf(w, xt[i][c], acc[i]);
    }
    if (e < DI) {
#pragma unroll
        for (int i = 0; i < 16; i++) {
            int m = m0 + i; int b = m / LL; int l = m % LL;
            g_xpre[(b*DI + e)*LL + l] = acc[i];
        }
    } else {
        int e2 = e - DI;
#pragma unroll
        for (int i = 0; i < 16; i++) g_z[(m0+i)*DI + e2] = acc[i];
    }
}

// ---------------- depthwise 3x3 conv + bias + silu + fused transpose --------
// one block per (b,d) image of 48x48
__global__ void __launch_bounds__(256) k_conv(const float* __restrict__ cw,
                                              const float* __restrict__ cb) {
    __shared__ float si[LL];
    __shared__ float so[48*49];
    int bd = blockIdx.x;
    int d  = bd % DI;
    int t  = threadIdx.x;
    const float* src = g_xpre + bd*LL;
    for (int i = t; i < LL; i += 256) si[i] = src[i];
    const float* wt = cw + d*9;
    float w0=wt[0],w1=wt[1],w2=wt[2],w3=wt[3],w4=wt[4],w5=wt[5],w6=wt[6],w7=wt[7],w8=wt[8];
    float bias = cb[d];
    __syncthreads();
    for (int i = t; i < LL; i += 256) {
        int h = (i*21846) >> 20;       // i/48
        int w = i - h*48;
        float s = bias;
        if (h > 0) {
            if (w > 0)  s = fmaf(si[i-49], w0, s);
                        s = fmaf(si[i-48], w1, s);
            if (w < 47) s = fmaf(si[i-47], w2, s);
        }
        if (w > 0)  s = fmaf(si[i-1], w3, s);
                    s = fmaf(si[i],   w4, s);
        if (w < 47) s = fmaf(si[i+1], w5, s);
        if (h < 47) {
            if (w > 0)  s = fmaf(si[i+47], w6, s);
                        s = fmaf(si[i+48], w7, s);
            if (w < 47) s = fmaf(si[i+49], w8, s);
        }
        s = s / (1.f + __expf(-s));    // silu
        g_conv[bd*LL + i] = s;
        so[h*49 + w] = s;
    }
    __syncthreads();
    float* dstT = g_convT + bd*LL;
    for (int j = t; j < LL; j += 256) {     // j = w*48 + h
        int w = (j*21846) >> 20;            // j/48
        int h = j - w*48;
        dstT[j] = so[h*49 + w];             // stride-49 read: conflict-free
    }
}

// ---------------- x_proj: x_dbl[b,k,c,l] = sum_d xs[b,k,d,l]*xpw[k,c,d] ------
// grid (36 l-tiles of 64, 2 axes, 2 b), block 256. 4 l per thread via float4.
#define LT 64
__global__ void __launch_bounds__(256) k_xdbl(const float* __restrict__ xpw) {
    __shared__ float tile[DI*LT];           // [d][64]  48KB
    int lt0  = blockIdx.x * LT;
    int axis = blockIdx.y;
    int b    = blockIdx.z;
    int t    = threadIdx.x;
    const float* src = (axis ? g_convT : g_conv) + b*DI*LL;
    for (int i = t; i < DI*(LT/4); i += 256) {
        int dd = i >> 4, c4 = i & 15;
        ((float4*)tile)[dd*16 + c4] = *(const float4*)(src + dd*LL + lt0 + c4*4);
    }
    __syncthreads();

    int lg  = t & 15;       // 4-l group
    int cgr = t >> 4;       // 0..15
    const float4* t4 = (const float4*)tile;
    for (int s = 0; s < 9; s++) {
        int c2 = cgr*9 + s;
        if (c2 >= 140) break;
        int flip = (c2 >= 70) ? 1 : 0;
        int c = c2 - 70*flip;
        int kk2 = axis + 2*flip;
        const float* wrow = xpw + (kk2*70 + c)*DI;
        float a0=0.f, a1=0.f, a2=0.f, a3=0.f;
#pragma unroll 4
        for (int dd = 0; dd < DI; dd++) {
            float w = wrow[dd];
            float4 xv = t4[dd*16 + lg];
            a0 = fmaf(w, xv.x, a0);
            a1 = fmaf(w, xv.y, a1);
            a2 = fmaf(w, xv.z, a2);
            a3 = fmaf(w, xv.w, a3);
        }
        float acc[4] = {a0, a1, a2, a3};
#pragma unroll
        for (int i2 = 0; i2 < 4; i2++) {
            int l  = lt0 + lg*4 + i2;
            int lo = flip ? (LL-1-l) : l;
            int bkl = (b*KK + kk2)*LL + lo;
            float v = acc[i2];
            if (c < RR)          g_dtr[bkl*RR + c]          = v;
            else if (c < RR+NS)  g_Bs [bkl*NS + (c-RR)]     = v;
            else                 g_Cs [bkl*NS + (c-RR-NS)]  = v;
        }
    }
}

// ---------------- dt expansion + softplus (fast math) ----------------
__global__ void __launch_bounds__(1024) k_delta(const float* __restrict__ dtw,
                                                const float* __restrict__ dtb) {
    int l  = blockIdx.x*32 + threadIdx.x;
    int d  = blockIdx.y*32 + threadIdx.y;
    int bk = blockIdx.z;
    int k  = bk % KK;
    const float* r = g_dtr + (bk*LL + l)*RR;
    const float* w = dtw + (k*DI + d)*RR;
    float acc = dtb[k*DI + d];
#pragma unroll
    for (int j = 0; j < RR; j++) acc = fmaf(r[j], w[j], acc);
    float sp = (acc > 15.f) ? acc : __logf(1.f + __expf(acc));
    g_delta[(bk*DI + d)*LL + l] = sp;
}

// ---------------- selective scan ----------------
// block = 8 warps = 8 consecutive d, same (b,k). lane = state.
// B/C tiles (shared by all d) staged via smem w/ register prefetch.
// per-step p=h*C staged in XOR-skewed smem; per-32-steps: row sums + 1 warp-wide RED.
__global__ void __launch_bounds__(256) k_scan(const float* __restrict__ A_logs,
                                              const float* __restrict__ Ds) {
    __shared__ float sB[32*NS];     // 4KB
    __shared__ float sC[32*NS];     // 4KB
    __shared__ float sp[8][32*32];  // 32KB, XOR-skewed
    int t = threadIdx.x, warp = t >> 5, lane = t & 31;
    int blk = blockIdx.x;           // 192 = 2b * 4k * 24dg
    int dg = blk % 24;
    int k  = (blk/24) & 3;
    int b  = blk / 96;
    int d  = dg*8 + warp;
    int kd = k*DI + d;

    float A  = -__expf(A_logs[kd*NS + lane]);
    float Dv = Ds[kd];
    const float* pd    = g_delta + ((b*KK + k)*DI + d)*LL;
    const float* baseB = g_Bs + (b*KK + k)*LL*NS;
    const float* baseC = g_Cs + (b*KK + k)*LL*NS;
    int axis = k & 1, rev = k >> 1;
    const float* pu = (axis ? g_convT : g_conv) + (b*DI + d)*LL;
    float* py = g_y + b*LL*DI + d;
    float* myp = sp[warp];

    float4 rB = *(const float4*)(baseB + t*4);
    float4 rC = *(const float4*)(baseC + t*4);
    float h = 0.f;
    for (int g = 0; g < 72; g++) {
        __syncthreads();                       // everyone done reading prev tile
        ((float4*)sB)[t] = rB;
        ((float4*)sC)[t] = rC;
        __syncthreads();                       // tile visible
        int gn = (g < 71) ? g + 1 : 71;
        rB = *(const float4*)(baseB + gn*(32*NS) + t*4);
        rC = *(const float4*)(baseC + gn*(32*NS) + t*4);

        int l0 = g * 32;
        float du = 0.f;
#pragma unroll
        for (int j = 0; j < 32; j++) {
            int l = l0 + j;
            float delta = pd[l];
            int m = rev ? (LL-1-l) : l;
            float u  = pu[m];
            float Bv = sB[j*NS + lane];
            float Cv = sC[j*NS + lane];
            float dA = __expf(delta * A);
            h = fmaf(h, dA, (delta*u)*Bv);
            myp[j*32 + (lane ^ j)] = h * Cv;   // skewed store: conflict-free
            if (j == lane) du = Dv * u;
        }
        __syncwarp();
        float s = du;
#pragma unroll
        for (int n = 0; n < 32; n++)
            s += myp[lane*32 + (n ^ lane)];    // skewed row sum: conflict-free
        int l = l0 + lane;
        int m = rev ? (LL-1-l) : l;
        int pos;
        if (axis == 0) pos = m;
        else { int q = (m*21846) >> 20; pos = (m - q*48)*48 + q; }
        atomicAdd(py + pos*DI, s);             // 1 warp-wide RED per 32 steps
        __syncwarp();
    }
}

// ---------------- LayerNorm + gate + out_proj + residual ----------------
__global__ void __launch_bounds__(192) k_final(const float* __restrict__ x,
                                               const float* __restrict__ lnw,
                                               const float* __restrict__ lnb,
                                               const float* __restrict__ Wo,
                                               float* __restrict__ out) {
    __shared__ float yg[DI];
    __shared__ float red[16];
    __shared__ float part[DI];
    int bl = blockIdx.x;
    int t  = threadIdx.x;

    float v = g_y[bl*DI + t];
    float s = v, ss = v*v;
#pragma unroll
    for (int o = 16; o > 0; o >>= 1) {
        s  += __shfl_xor_sync(0xffffffffu, s,  o);
        ss += __shfl_xor_sync(0xffffffffu, ss, o);
    }
    if ((t & 31) == 0) { red[t>>5] = s; red[8 + (t>>5)] = ss; }
    __syncthreads();
    if (t == 0) {
        float S = 0.f, SS = 0.f;
        for (int i = 0; i < 6; i++) { S += red[i]; SS += red[8+i]; }
        red[14] = S; red[15] = SS;
    }
    __syncthreads();
    float mu  = red[14] * (1.f/DI);
    float var = red[15] * (1.f/DI) - mu*mu;
    float inv = rsqrtf(var + 1e-5f);
    float z   = g_z[bl*DI + t];
    float sil = z / (1.f + __expf(-z));
    yg[t] = ((v - mu)*inv*lnw[t] + lnb[t]) * sil;
    __syncthreads();

    int c  = (t < 96) ? t : t - 96;
    int h0 = (t < 96) ? 0 : 96;
    const float* wr = Wo + c*DI + h0;
    float acc = 0.f;
#pragma unroll 8
    for (int dd = 0; dd < 96; dd++) acc = fmaf(yg[h0 + dd], wr[dd], acc);
    part[t] = acc;
    __syncthreads();
    if (t < 96) out[bl*CC + t] = x[bl*CC + t] + part[t] + part[t + 96];
}

// ---------------- launch ----------------
extern "C" void kernel_launch(void* const* d_in, const int* in_sizes, int n_in,
                              void* d_out, int out_size) {
    const float* x    = (const float*)d_in[0];
    const float* ipw  = (const float*)d_in[1];
    const float* cw   = (const float*)d_in[2];
    const float* cb   = (const float*)d_in[3];
    const float* xpw  = (const float*)d_in[4];
    const float* dtw  = (const float*)d_in[5];
    const float* dtb  = (const float*)d_in[6];
    const float* alog = (const float*)d_in[7];
    const float* Dsp  = (const float*)d_in[8];
    const float* lnw  = (const float*)d_in[9];
    const float* lnb  = (const float*)d_in[10];
    const float* Wo   = (const float*)d_in[11];
    float* out = (float*)d_out;

    k_zero  <<<864, 1024>>>();
    k_inproj<<<288, 384>>>(x, ipw);
    k_conv  <<<BB*DI, 256>>>(cw, cb);
    k_xdbl  <<<dim3(36, 2, 2), 256>>>(xpw);
    k_delta <<<dim3(72, 6, 8), dim3(32, 32)>>>(dtw, dtb);
    k_scan  <<<192, 256>>>(alog, Dsp);
    k_final <<<BB*LL, 192>>>(x, lnw, lnb, Wo, out);
}